// round 3
// baseline (speedup 1.0000x reference)
#include <cuda_runtime.h>
#include <cstdint>

// Problem constants
#define T_STEPS 512
#define BATCH   32
#define DIM     512
#define HID     256
#define A1N     16
#define A2N     128

typedef unsigned long long ull;

// ---------------- device scratch (allocation-free rule: __device__ globals) ----
__device__ float g_lut[8200];                    // exp(f(x)) lookup table
__device__ float g_seq[T_STEPS * BATCH];         // stage-1 output (T,B)
__device__ float g_hs [T_STEPS * BATCH * HID];   // LSTM hidden history (T,B,H)
__device__ float g_s2 [T_STEPS * BATCH];         // stage-3 logits (T,B)

// =============================================================================
// K0: build LUT  g(x) = exp( sum_a u1[a] * tanh(x*W1[a] + b1[a]) ),  x in [-8,8]
// =============================================================================
__global__ void k0_lut(const float* __restrict__ W1,
                       const float* __restrict__ b1,
                       const float* __restrict__ u1) {
    int i = blockIdx.x * blockDim.x + threadIdx.x;
    if (i > 8192) return;
    float x = -8.f + (float)i * (16.f / 8192.f);
    float f = 0.f;
#pragma unroll
    for (int a = 0; a < A1N; a++)
        f += u1[a] * tanhf(x * W1[a] + b1[a]);
    g_lut[i] = expf(f);
}

// =============================================================================
// K1: AttLayer1 soft pool over D.  seq[t,b] = sum_d x*g(x) / sum_d g(x)
// =============================================================================
__global__ __launch_bounds__(256) void k1_att1(const float* __restrict__ x) {
    __shared__ float lut[8193];
    for (int i = threadIdx.x; i < 8193; i += 256) lut[i] = g_lut[i];
    __syncthreads();

    int warp = threadIdx.x >> 5, lane = threadIdx.x & 31;
#pragma unroll
    for (int q = 0; q < 4; q++) {
        int pair = blockIdx.x * 32 + warp * 4 + q;     // pair = t*B + b
        const float* xp = x + (size_t)pair * DIM;
        float aw = 0.f, axw = 0.f;
#pragma unroll 4
        for (int d = lane; d < DIM; d += 32) {
            float v = xp[d];
            float pos = (v + 8.f) * 512.f;             // 8192/16 per unit x
            pos = fminf(fmaxf(pos, 0.f), 8191.0f);
            int   i0 = (int)pos;
            float fr = pos - (float)i0;
            float g0 = lut[i0], g1 = lut[i0 + 1];
            float g  = g0 + fr * (g1 - g0);
            aw  += g;
            axw += v * g;
        }
#pragma unroll
        for (int o = 16; o > 0; o >>= 1) {
            aw  += __shfl_xor_sync(0xFFFFFFFFu, aw,  o);
            axw += __shfl_xor_sync(0xFFFFFFFFu, axw, o);
        }
        if (lane == 0) g_seq[pair] = axw / aw;
    }
}

// =============================================================================
// K2: LSTM recurrence.  16 clusters x 8 CTAs. Cluster c owns batches 2c, 2c+1.
// CTA rank r owns h-units [32r, 32r+32) -> 128 gate rows (4 gates x 32 units).
// Weights register-resident; f32x2 FMA mainloop.
// h exchange: publish to own smem -> cluster.sync -> gather via mapa/ld.
// =============================================================================
__device__ __forceinline__ unsigned smem_u32(const void* p) {
    unsigned a;
    asm("{ .reg .u64 t; cvta.to.shared.u64 t, %1; cvt.u32.u64 %0, t; }"
        : "=r"(a) : "l"(p));
    return a;
}

__global__ void __cluster_dims__(8, 1, 1) __launch_bounds__(256, 1)
k2_lstm(const float* __restrict__ Whh, const float* __restrict__ Wih,
        const float* __restrict__ bih, const float* __restrict__ bhh,
        const float* __restrict__ h0,  const float* __restrict__ c0) {
    // hbuf[ph][p] = {b0[2p], b0[2p+1], b1[2p], b1[2p+1]}  (gathered, full H)
    __shared__ float4 hbuf[2][128];
    // hpub[ph][batch][unit_local] : this CTA's published h values
    __shared__ float  hpub[2][2][32];
    __shared__ float  psum[2][128][2];   // [khalf][local gate row][batch]
    __shared__ float  sq[2][T_STEPS];    // seq for the 2 batches

    const int tid = threadIdx.x;
    unsigned rank;
    asm("mov.u32 %0, %%cluster_ctarank;" : "=r"(rank));
    const int cid = blockIdx.x >> 3;
    const int b0g = cid * 2;

    const int l  = tid & 127;   // local gate row: gate = l>>5, unit = l&31
    const int kh = tid >> 7;    // k-half (0: k 0..127, 1: k 128..255)
    const int grow = (l >> 5) * HID + (int)rank * 32 + (l & 31);

    // ---- register-resident weights: 64 packed f32x2 (128 floats) -------------
    ull w[64];
    const ull* wrow = reinterpret_cast<const ull*>(Whh) + (size_t)grow * 128 + kh * 64;
#pragma unroll
    for (int j = 0; j < 64; j++) w[j] = wrow[j];

    const float bsum = bih[grow] + bhh[grow];
    const float wih  = Wih[grow];

    // ---- preload seq (both batches) ------------------------------------------
    for (int i = tid; i < 2 * T_STEPS; i += 256) {
        int bb = i >> 9, tt = i & 511;
        sq[bb][tt] = g_seq[tt * BATCH + b0g + bb];
    }
    // ---- fill hbuf[0] locally from h0 (no comms needed at step 0) ------------
    for (int i = tid; i < 2 * HID; i += 256) {
        int bb = i >> 8, U = i & 255;
        ((float*)&hbuf[0][U >> 1])[(U & 1) + 2 * bb] = h0[(b0g + bb) * HID + U];
    }
    // ---- updater state: threads 0..63 own (batch = tid>>5, unit = tid&31) ----
    const int ubatch = tid >> 5, uu = tid & 31;
    float creg = 0.f;
    if (tid < 64) creg = c0[(b0g + ubatch) * HID + (int)rank * 32 + uu];
    __syncthreads();

    // gather plan for this thread: 2 elements (i = tid, tid+256)
    const int gi0_bb = tid >> 8, gi0_U = tid & 255;            // always bb=0
    const int gi1_bb = (tid + 256) >> 8, gi1_U = (tid + 256) & 255; // bb=1
    const unsigned hpub_base = smem_u32(&hpub[0][0][0]);

    for (int t = 0; t < T_STEPS; t++) {
        const int ph = t & 1, nph = ph ^ 1;

        // ---- gate GEMV fragment: dot over this thread's 128-k half -----------
        const ulonglong2* hp =
            reinterpret_cast<const ulonglong2*>(&hbuf[ph][kh * 64]);
        ull a0 = 0ULL, a1 = 0ULL;
#pragma unroll
        for (int j = 0; j < 64; j++) {
            ulonglong2 h2 = hp[j];
            asm("fma.rn.f32x2 %0, %1, %2, %0;" : "+l"(a0) : "l"(w[j]), "l"(h2.x));
            asm("fma.rn.f32x2 %0, %1, %2, %0;" : "+l"(a1) : "l"(w[j]), "l"(h2.y));
        }
        float s0lo, s0hi, s1lo, s1hi;
        asm("mov.b64 {%0,%1}, %2;" : "=f"(s0lo), "=f"(s0hi) : "l"(a0));
        asm("mov.b64 {%0,%1}, %2;" : "=f"(s1lo), "=f"(s1hi) : "l"(a1));
        float s0 = s0lo + s0hi;
        float s1 = s1lo + s1hi;
        if (kh == 0) {
            s0 += bsum + wih * sq[0][t];
            s1 += bsum + wih * sq[1][t];
        }
        psum[kh][l][0] = s0;
        psum[kh][l][1] = s1;
        __syncthreads();

        // ---- state update (64 threads); publish to OWN smem ------------------
        if (tid < 64) {
            float gi = psum[0][uu][ubatch]      + psum[1][uu][ubatch];
            float gf = psum[0][32 + uu][ubatch] + psum[1][32 + uu][ubatch];
            float gg = psum[0][64 + uu][ubatch] + psum[1][64 + uu][ubatch];
            float go = psum[0][96 + uu][ubatch] + psum[1][96 + uu][ubatch];
            float ci = 1.f / (1.f + expf(-gi));
            float cf = 1.f / (1.f + expf(-gf));
            float co = 1.f / (1.f + expf(-go));
            creg = cf * creg + ci * tanhf(gg);
            float hv = co * tanhf(creg);

            hpub[nph][ubatch][uu] = hv;
            g_hs[((size_t)t * BATCH + b0g + ubatch) * HID + (int)rank * 32 + uu] = hv;
        }

        // ---- cluster barrier: release own hpub writes, acquire peers' --------
        asm volatile("barrier.cluster.arrive.aligned;" ::: "memory");
        asm volatile("barrier.cluster.wait.aligned;"   ::: "memory");

        // ---- gather full h (2 batches x 256 units) into hbuf[nph] ------------
        {
            // element 0: bb=0, U = gi0_U
            unsigned la0 = hpub_base +
                (unsigned)((nph * 64 + gi0_bb * 32 + (gi0_U & 31)) * 4);
            unsigned ra0;
            asm("mapa.shared::cluster.u32 %0, %1, %2;"
                : "=r"(ra0) : "r"(la0), "r"(gi0_U >> 5));
            float v0;
            asm volatile("ld.shared::cluster.f32 %0, [%1];" : "=f"(v0) : "r"(ra0));
            ((float*)&hbuf[nph][gi0_U >> 1])[(gi0_U & 1) + 2 * gi0_bb] = v0;

            // element 1: bb=1, U = gi1_U
            unsigned la1 = hpub_base +
                (unsigned)((nph * 64 + gi1_bb * 32 + (gi1_U & 31)) * 4);
            unsigned ra1;
            asm("mapa.shared::cluster.u32 %0, %1, %2;"
                : "=r"(ra1) : "r"(la1), "r"(gi1_U >> 5));
            float v1;
            asm volatile("ld.shared::cluster.f32 %0, [%1];" : "=f"(v1) : "r"(ra1));
            ((float*)&hbuf[nph][gi1_U >> 1])[(gi1_U & 1) + 2 * gi1_bb] = v1;
        }
        __syncthreads();   // hbuf[nph] ready for next step; psum reusable
    }
}

// =============================================================================
// K3: AttLayer2 logits.  s2[t,b] = sum_a u2[a]*tanh( hs[t,b,:]@W2[:,a] + b2[a] )
// 128 CTAs: (b, t-quarter). 8x8 register tiles, f32x2.
// =============================================================================
__global__ __launch_bounds__(256) void k3_att2(const float* __restrict__ W2,
                                               const float* __restrict__ b2,
                                               const float* __restrict__ u2) {
    __shared__ float sh[128][33];   // [t-local][k]  (padded)
    __shared__ float sw[32][128];   // [k][a]
    __shared__ float sp[128][17];   // partial [t-local][tx]
    __shared__ float sb2[A2N], su2[A2N];

    const int tid = threadIdx.x;
    const int b = blockIdx.x & 31, tq = blockIdx.x >> 5;
    const int t0 = tq * 128;
    if (tid < A2N) { sb2[tid] = b2[tid]; su2[tid] = u2[tid]; }

    const int tx = tid & 15;   // a-group (8 a's each)
    const int ty = tid >> 4;   // t-group (8 t's each)

    ull acc[8][4];
#pragma unroll
    for (int i = 0; i < 8; i++)
#pragma unroll
        for (int p = 0; p < 4; p++) acc[i][p] = 0ULL;

    for (int kc = 0; kc < 8; kc++) {
        __syncthreads();
        for (int idx = tid; idx < 4096; idx += 256) {
            int tl = idx >> 5, k = idx & 31;
            sh[tl][k] = g_hs[((size_t)(t0 + tl) * BATCH + b) * HID + kc * 32 + k];
        }
        for (int idx = tid; idx < 4096; idx += 256) {
            int k = idx >> 7, a = idx & 127;
            sw[k][a] = W2[(kc * 32 + k) * A2N + a];
        }
        __syncthreads();
#pragma unroll 4
        for (int k = 0; k < 32; k++) {
            const ull* wv = reinterpret_cast<const ull*>(&sw[k][tx * 8]);
            ull w0 = wv[0], w1 = wv[1], w2_ = wv[2], w3 = wv[3];
#pragma unroll
            for (int i = 0; i < 8; i++) {
                float hvv = sh[ty * 8 + i][k];
                ull hh;
                asm("mov.b64 %0, {%1,%1};" : "=l"(hh) : "f"(hvv));
                asm("fma.rn.f32x2 %0, %1, %2, %0;" : "+l"(acc[i][0]) : "l"(w0),  "l"(hh));
                asm("fma.rn.f32x2 %0, %1, %2, %0;" : "+l"(acc[i][1]) : "l"(w1),  "l"(hh));
                asm("fma.rn.f32x2 %0, %1, %2, %0;" : "+l"(acc[i][2]) : "l"(w2_), "l"(hh));
                asm("fma.rn.f32x2 %0, %1, %2, %0;" : "+l"(acc[i][3]) : "l"(w3),  "l"(hh));
            }
        }
    }
    // epilogue: tanh + u2 dot over this thread's 8 a's
    float sres[8];
#pragma unroll
    for (int i = 0; i < 8; i++) sres[i] = 0.f;
#pragma unroll
    for (int i = 0; i < 8; i++) {
#pragma unroll
        for (int p = 0; p < 4; p++) {
            float lo, hi;
            asm("mov.b64 {%0,%1}, %2;" : "=f"(lo), "=f"(hi) : "l"(acc[i][p]));
            int a0 = tx * 8 + p * 2;
            sres[i] += su2[a0]     * tanhf(lo + sb2[a0]);
            sres[i] += su2[a0 + 1] * tanhf(hi + sb2[a0 + 1]);
        }
    }
#pragma unroll
    for (int i = 0; i < 8; i++) sp[ty * 8 + i][tx] = sres[i];
    __syncthreads();
    if (tid < 128) {
        float s = 0.f;
#pragma unroll
        for (int xx = 0; xx < 16; xx++) s += sp[tid][xx];
        g_s2[(t0 + tid) * BATCH + b] = s;
    }
}

// =============================================================================
// K4: softmax over T, attention pool, linear head.  One CTA per batch.
// =============================================================================
__global__ __launch_bounds__(256) void k4_final(const float* __restrict__ Wl,
                                                const float* __restrict__ bl,
                                                float* __restrict__ out) {
    __shared__ float a2s[T_STEPS];
    __shared__ float red[256];
    const int b = blockIdx.x, tid = threadIdx.x;

    for (int t = tid; t < T_STEPS; t += 256)
        a2s[t] = expf(g_s2[t * BATCH + b]);
    __syncthreads();

    float p = a2s[tid] + a2s[tid + 256];
    red[tid] = p;
    __syncthreads();
#pragma unroll
    for (int o = 128; o > 0; o >>= 1) {
        if (tid < o) red[tid] += red[tid + o];
        __syncthreads();
    }
    const float inv = 1.f / red[0];
    __syncthreads();

    // pooled[u] = sum_t a2[t] * hs[t][b][u]   (tid = u)
    float acc = 0.f;
    const float* hp = g_hs + (size_t)b * HID + tid;
#pragma unroll 8
    for (int t = 0; t < T_STEPS; t++)
        acc += a2s[t] * hp[(size_t)t * BATCH * HID];
    acc *= inv;

    float v = acc * Wl[tid];
    red[tid] = v;
    __syncthreads();
#pragma unroll
    for (int o = 128; o > 0; o >>= 1) {
        if (tid < o) red[tid] += red[tid + o];
        __syncthreads();
    }
    if (tid == 0) out[b] = red[0] + bl[0];
}

// =============================================================================
// launcher
// =============================================================================
extern "C" void kernel_launch(void* const* d_in, const int* in_sizes, int n_in,
                              void* d_out, int out_size) {
    const float* inputs = (const float*)d_in[0];
    const float* W1  = (const float*)d_in[1];
    const float* b1  = (const float*)d_in[2];
    const float* u1  = (const float*)d_in[3];
    const float* Wih = (const float*)d_in[4];
    const float* Whh = (const float*)d_in[5];
    const float* bih = (const float*)d_in[6];
    const float* bhh = (const float*)d_in[7];
    const float* h0  = (const float*)d_in[8];
    const float* c0  = (const float*)d_in[9];
    const float* W2  = (const float*)d_in[10];
    const float* b2  = (const float*)d_in[11];
    const float* u2  = (const float*)d_in[12];
    const float* Wl  = (const float*)d_in[13];
    const float* bl  = (const float*)d_in[14];
    float* out = (float*)d_out;

    k0_lut  <<<33, 256>>>(W1, b1, u1);
    k1_att1 <<<512, 256>>>(inputs);
    k2_lstm <<<128, 256>>>(Whh, Wih, bih, bhh, h0, c0);
    k3_att2 <<<128, 256>>>(W2, b2, u2);
    k4_final<<<32, 256>>>(Wl, bl, out);
}